// round 9
// baseline (speedup 1.0000x reference)
#include <cuda_runtime.h>
#include <cuda_fp16.h>
#include <cstdint>

// ---------------------------------------------------------------------------
// Problem constants
// ---------------------------------------------------------------------------
#define M_DIM 16384   // B*S = 8*2048
#define N_DIM 4096    // OUT
#define K_DIM 4096    // IN
#define KE    4224    // extended K: 4096 + 8 adapters * 16 rank
#define BK    64
#define KT_CNT 66     // KE / 64
#define S_LEN 2048
#define R_RANK 16

// ---------------------------------------------------------------------------
// Device-global scratch
//  g_t  : t = x @ lora_a^T, fp32 [M, 16]
//  g_xe : A image, fp16 + K-extended + FRAGMENT-PACKED (m16n8k16 layout)
//         [mtile(128)][ktile(66)] x 16KB tiles (8192 halves)
//  g_we : B image likewise: [ntile(32)][ktile(66)] x 16KB tiles
// ---------------------------------------------------------------------------
__device__ float g_t[M_DIM * R_RANK];
__device__ __align__(1024) __half g_xe[(size_t)128 * KT_CNT * 8192];
__device__ __align__(1024) __half g_we[(size_t)32  * KT_CNT * 8192];

__device__ __forceinline__ uint32_t pack2(float lo, float hi) {
    __half2 h = __floats2half2_rn(lo, hi);
    return *(uint32_t*)&h;
}

// ---------------------------------------------------------------------------
// Kernel 1: t[m, r] = sum_k x[m,k] * lora_a[adapter(m)][r][k]   (fp32 exact)
// ---------------------------------------------------------------------------
__global__ __launch_bounds__(256) void lora_t_kernel(const float* __restrict__ x,
                                                     const float* __restrict__ la) {
    const int warp = threadIdx.x >> 5;
    const int lane = threadIdx.x & 31;
    const int m0 = blockIdx.x * 32 + warp * 4;
    const int adapter = m0 / S_LEN;
    const float* lap = la + (size_t)adapter * R_RANK * K_DIM;

    float acc[4][R_RANK];
#pragma unroll
    for (int rr = 0; rr < 4; rr++)
#pragma unroll
        for (int r = 0; r < R_RANK; r++) acc[rr][r] = 0.f;

    for (int kk = lane; kk < K_DIM / 4; kk += 32) {
        const int k = kk * 4;
        float4 xv[4];
#pragma unroll
        for (int rr = 0; rr < 4; rr++)
            xv[rr] = *(const float4*)(x + (size_t)(m0 + rr) * K_DIM + k);
#pragma unroll
        for (int r = 0; r < R_RANK; r++) {
            const float4 av = *(const float4*)(lap + (size_t)r * K_DIM + k);
#pragma unroll
            for (int rr = 0; rr < 4; rr++) {
                acc[rr][r] += xv[rr].x * av.x;
                acc[rr][r] += xv[rr].y * av.y;
                acc[rr][r] += xv[rr].z * av.z;
                acc[rr][r] += xv[rr].w * av.w;
            }
        }
    }
#pragma unroll
    for (int off = 16; off > 0; off >>= 1)
#pragma unroll
        for (int rr = 0; rr < 4; rr++)
#pragma unroll
            for (int r = 0; r < R_RANK; r++)
                acc[rr][r] += __shfl_xor_sync(0xffffffffu, acc[rr][r], off);
    if (lane < R_RANK) {
#pragma unroll
        for (int rr = 0; rr < 4; rr++)
            g_t[(m0 + rr) * R_RANK + lane] = acc[rr][lane];
    }
}

// ---------------------------------------------------------------------------
// Kernel 2: build A image — SMEM-STAGED for coalesced global reads.
// One block = one (mtile, ktile): load 128x64 fp32 coalesced -> smem,
// then emit 1024 fragment-packed 16B units coalesced.
// ---------------------------------------------------------------------------
__global__ __launch_bounds__(256) void ext_a_kernel(const float* __restrict__ x) {
    __shared__ float sx[128][66];   // 64 cols + pad 2 (even stride for float2)
    const int tid = threadIdx.x;
    const uint32_t ktile = blockIdx.x;
    const uint32_t mtile = blockIdx.y;
    const uint32_t k0 = ktile * 64;
    const uint32_t ad = mtile >> 4;   // adapter uniform over 128-row tile

    if (k0 < K_DIM) {
#pragma unroll
        for (int i = 0; i < 8; i++) {
            const int idx = tid + i * 256;       // 2048 float4 slots
            const int row = idx >> 4;
            const int c4 = (idx & 15) * 4;
            const float4 v = *(const float4*)(x + (size_t)(mtile * 128 + row) * K_DIM + k0 + c4);
            sx[row][c4] = v.x; sx[row][c4 + 1] = v.y;
            sx[row][c4 + 2] = v.z; sx[row][c4 + 3] = v.w;
        }
    } else {
#pragma unroll
        for (int i = 0; i < 8; i++) {
            const int idx = tid + i * 256;
            const int row = idx >> 4;
            const int c4 = (idx & 15) * 4;
            const uint32_t e = k0 + c4 - K_DIM;   // 16-block aligned: one adapter
            const uint32_t a = e >> 4, r = e & 15;
            float4 v = make_float4(0.f, 0.f, 0.f, 0.f);
            if (a == ad) {
                const float4 t = *(const float4*)(g_t + (size_t)(mtile * 128 + row) * R_RANK + r);
                v = make_float4(2.f * t.x, 2.f * t.y, 2.f * t.z, 2.f * t.w);
            }
            sx[row][c4] = v.x; sx[row][c4 + 1] = v.y;
            sx[row][c4 + 2] = v.z; sx[row][c4 + 3] = v.w;
        }
    }
    __syncthreads();

    __half* dst = g_xe + (size_t)(mtile * KT_CNT + ktile) * 8192;
#pragma unroll
    for (int j = 0; j < 4; j++) {
        const uint32_t u = tid + j * 256;
        const uint32_t lane = u & 31;
        const uint32_t ks = (u >> 5) & 3;
        const uint32_t mt = (u >> 7) & 3;
        const uint32_t wm = (u >> 9) & 1;
        const uint32_t g = lane >> 2, tg = lane & 3;
        const uint32_t r0 = wm * 64 + mt * 16 + g;
        const uint32_t kk = ks * 16 + 2 * tg;

        const float2 p00 = *(const float2*)&sx[r0][kk];
        const float2 p10 = *(const float2*)&sx[r0 + 8][kk];
        const float2 p01 = *(const float2*)&sx[r0][kk + 8];
        const float2 p11 = *(const float2*)&sx[r0 + 8][kk + 8];
        uint4 v;
        v.x = pack2(p00.x, p00.y);
        v.y = pack2(p10.x, p10.y);
        v.z = pack2(p01.x, p01.y);
        v.w = pack2(p11.x, p11.y);
        *(uint4*)(dst + u * 8) = v;
    }
}

// ---------------------------------------------------------------------------
// Kernel 3: build B image (fp16, fragment-packed, K-extended)
// ---------------------------------------------------------------------------
__global__ __launch_bounds__(256) void ext_b_kernel(const float* __restrict__ W,
                                                    const float* __restrict__ lb) {
    const uint32_t idx = blockIdx.x * 256 + threadIdx.x;  // < 32*66*1024
    const uint32_t u = idx & 1023;
    const uint32_t tile = idx >> 10;
    const uint32_t ntile = tile / KT_CNT;
    const uint32_t ktile = tile % KT_CNT;

    const uint32_t lane = u & 31;
    const uint32_t ks = (u >> 5) & 3;
    const uint32_t ntp = (u >> 7) & 1;
    const uint32_t wn = (u >> 8) & 3;
    const uint32_t g = lane >> 2, tg = lane & 3;

    const uint32_t c0 = ntile * 128 + wn * 32 + ntp * 16 + g;  // cols c0, c0+8
    const uint32_t k0 = ktile * 64 + ks * 16 + 2 * tg;

    uint4 v;
    if (k0 < K_DIM) {
        const float2 p00 = *(const float2*)(W + (size_t)c0 * K_DIM + k0);
        const float2 p01 = *(const float2*)(W + (size_t)c0 * K_DIM + k0 + 8);
        const float2 p10 = *(const float2*)(W + (size_t)(c0 + 8) * K_DIM + k0);
        const float2 p11 = *(const float2*)(W + (size_t)(c0 + 8) * K_DIM + k0 + 8);
        v.x = pack2(p00.x, p00.y);
        v.y = pack2(p01.x, p01.y);
        v.z = pack2(p10.x, p10.y);
        v.w = pack2(p11.x, p11.y);
    } else {
        const uint32_t e = k0 - K_DIM;
        const uint32_t a = e >> 4, r = e & 15;
        const float* p0 = lb + ((size_t)a * N_DIM + c0) * R_RANK;
        const float* p1 = lb + ((size_t)a * N_DIM + c0 + 8) * R_RANK;
        v.x = pack2(p0[r], p0[r + 1]);
        v.y = pack2(p0[r + 8], p0[r + 9]);
        v.z = pack2(p1[r], p1[r + 1]);
        v.w = pack2(p1[r + 8], p1[r + 9]);
    }
    *(uint4*)(g_we + (size_t)tile * 8192 + u * 8) = v;
}

// ---------------------------------------------------------------------------
// Kernel 4: GEMM. 128x256 block tile, 8 warps of 64x64, fp16 m16n8k16,
// 4-stage cp.async pipeline (192KB smem, 1 CTA/SM).
// Per warp-ktile: 32 LDS.128 + 128 MMA  (MMA:LDS = 4).
// ---------------------------------------------------------------------------
#define STAGES 4
#define A_BYTES 16384
#define STAGE_BYTES 49152                       // A 16KB + B 32KB
#define SMEM_BYTES (STAGES * STAGE_BYTES)       // 196608

__device__ __forceinline__ void mma_f16(float* c, const uint32_t* a, const uint32_t* b) {
    asm volatile(
        "mma.sync.aligned.m16n8k16.row.col.f32.f16.f16.f32 "
        "{%0,%1,%2,%3}, {%4,%5,%6,%7}, {%8,%9}, {%0,%1,%2,%3};"
        : "+f"(c[0]), "+f"(c[1]), "+f"(c[2]), "+f"(c[3])
        : "r"(a[0]), "r"(a[1]), "r"(a[2]), "r"(a[3]), "r"(b[0]), "r"(b[1]));
}

__global__ __launch_bounds__(256, 1) void lora_gemm_kernel(float* __restrict__ out) {
    extern __shared__ char smem[];
    const int tid = threadIdx.x;
    const int lane = tid & 31;
    const int warp = tid >> 5;
    const int warp_m = warp >> 2;   // 0..1 : 64 rows each
    const int warp_n = warp & 3;    // 0..3 : 64 cols each
    const int g = lane >> 2;
    const int tg = lane & 3;
    const uint32_t mtile = blockIdx.y;
    const uint32_t nt2 = blockIdx.x;   // 256-wide N tile

    float acc[4][8][4];
#pragma unroll
    for (int mt = 0; mt < 4; mt++)
#pragma unroll
        for (int nt = 0; nt < 8; nt++)
#pragma unroll
            for (int c = 0; c < 4; c++) acc[mt][nt][c] = 0.f;

    const char* gA = (const char*)g_xe + ((size_t)mtile * KT_CNT << 14);
    const char* gB0 = (const char*)g_we + ((size_t)(nt2 * 2) * KT_CNT << 14);
    const char* gB1 = (const char*)g_we + ((size_t)(nt2 * 2 + 1) * KT_CNT << 14);

    auto load_tile = [&](int stage, int kt) {
        char* st = smem + stage * STAGE_BYTES;
        const size_t ko = (size_t)kt << 14;
#pragma unroll
        for (int i = 0; i < 4; i++) {
            const int off = (tid + i * 256) * 16;
            uint32_t d = (uint32_t)__cvta_generic_to_shared(st + off);
            asm volatile("cp.async.cg.shared.global [%0], [%1], 16;" ::"r"(d), "l"(gA + ko + off));
        }
#pragma unroll
        for (int i = 0; i < 4; i++) {
            const int off = (tid + i * 256) * 16;
            uint32_t d = (uint32_t)__cvta_generic_to_shared(st + A_BYTES + off);
            asm volatile("cp.async.cg.shared.global [%0], [%1], 16;" ::"r"(d), "l"(gB0 + ko + off));
        }
#pragma unroll
        for (int i = 0; i < 4; i++) {
            const int off = (tid + i * 256) * 16;
            uint32_t d = (uint32_t)__cvta_generic_to_shared(st + A_BYTES + 16384 + off);
            asm volatile("cp.async.cg.shared.global [%0], [%1], 16;" ::"r"(d), "l"(gB1 + ko + off));
        }
    };

    auto compute_tile = [&](int stage) {
        const char* sA = smem + stage * STAGE_BYTES;
        const char* sB = sA + A_BYTES + (warp_n >> 1) * 16384;
        const int wnb = (warp_n & 1) * 2;
#pragma unroll
        for (int ks = 0; ks < 4; ks++) {
            uint4 af[4];
#pragma unroll
            for (int mt = 0; mt < 4; mt++)
                af[mt] = *(const uint4*)(sA + (((warp_m * 4 + mt) * 4 + ks) * 32 + lane) * 16);
            uint4 bv[2][2];
#pragma unroll
            for (int s = 0; s < 2; s++)
#pragma unroll
                for (int ntp = 0; ntp < 2; ntp++)
                    bv[s][ntp] = *(const uint4*)(
                        sB + ((((wnb + s) * 2 + ntp) * 4 + ks) * 32 + lane) * 16);
#pragma unroll
            for (int mt = 0; mt < 4; mt++)
#pragma unroll
                for (int nt = 0; nt < 8; nt++) {
                    const int s = nt >> 2, ntp = (nt >> 1) & 1;
                    uint32_t b[2];
                    if (nt & 1) { b[0] = bv[s][ntp].z; b[1] = bv[s][ntp].w; }
                    else        { b[0] = bv[s][ntp].x; b[1] = bv[s][ntp].y; }
                    mma_f16(acc[mt][nt], (const uint32_t*)&af[mt], b);
                }
        }
    };

#pragma unroll
    for (int s = 0; s < STAGES - 1; s++) {
        load_tile(s, s);
        asm volatile("cp.async.commit_group;");
    }
    for (int kt = 0; kt < KT_CNT; kt++) {
        asm volatile("cp.async.wait_group %0;" ::"n"(STAGES - 2));
        __syncthreads();
        const int nxt = kt + STAGES - 1;
        if (nxt < KT_CNT) load_tile(nxt % STAGES, nxt);
        asm volatile("cp.async.commit_group;");
        compute_tile(kt % STAGES);
    }

    // ---- pure-store epilogue (LoRA already folded into K) ----
#pragma unroll
    for (int mt = 0; mt < 4; mt++)
#pragma unroll
        for (int i = 0; i < 2; i++) {
            const size_t row = (size_t)mtile * 128 + warp_m * 64 + mt * 16 + g + i * 8;
#pragma unroll
            for (int nt = 0; nt < 8; nt++) {
                const uint32_t col = nt2 * 256 + warp_n * 64 + nt * 8 + tg * 2;
                *(float2*)&out[row * N_DIM + col] =
                    make_float2(acc[mt][nt][i * 2 + 0], acc[mt][nt][i * 2 + 1]);
            }
        }
}

// ---------------------------------------------------------------------------
// Harness entry
// d_in[0]=data [8,2048,4096] f32, d_in[1]=W [4096,4096] f32,
// d_in[2]=lora_a [8,16,4096] f32, d_in[3]=lora_b [8,4096,16] f32
// ---------------------------------------------------------------------------
extern "C" void kernel_launch(void* const* d_in, const int* in_sizes, int n_in,
                              void* d_out, int out_size) {
    const float* x = (const float*)d_in[0];
    const float* W = (const float*)d_in[1];
    const float* la = (const float*)d_in[2];
    const float* lb = (const float*)d_in[3];
    float* out = (float*)d_out;

    cudaFuncSetAttribute(lora_gemm_kernel,
                         cudaFuncAttributeMaxDynamicSharedMemorySize, SMEM_BYTES);

    lora_t_kernel<<<M_DIM / 32, 256>>>(x, la);
    {
        dim3 ga(KT_CNT, M_DIM / 128);   // (66, 128)
        ext_a_kernel<<<ga, 256>>>(x);
    }
    ext_b_kernel<<<(32 * KT_CNT * 1024) / 256, 256>>>(W, lb);

    dim3 grid(N_DIM / 256, M_DIM / 128);  // (16, 128)
    lora_gemm_kernel<<<grid, 256, SMEM_BYTES>>>(out);
}